// round 12
// baseline (speedup 1.0000x reference)
#include <cuda_runtime.h>
#include <cuda_fp16.h>
#include <stdint.h>

// Problem constants (fixed by the reference)
#define NN    32768
#define EE    262144
#define OUTD  512
#define HH    8
#define DHH   64

// ---------------- scratch (device globals; no allocation allowed) ----------
__device__ float  g_wr[4 * OUTD * OUTD];   // RNA-rounded weights
__device__ float  g_x[NN * OUTD];          // x, stored already tf32-rounded
__device__ __half g_q[NN * OUTD];          // q/k/v stored fp16 (RN)
__device__ __half g_k[NN * OUTD];
__device__ __half g_v[NN * OUTD];
__device__ int    g_cnt[NN];
__device__ int    g_off[NN + 1];
__device__ int    g_cur[NN];
__device__ int    g_ecol[EE];

// ---------------- tf32 helpers ---------------------------------------------
__device__ __forceinline__ float cvt_rna_tf32(float x)
{
    float r;
    asm("cvt.rna.tf32.f32 %0, %1;" : "=f"(r) : "f"(x));
    return r;
}

__device__ __forceinline__ void mma_tf32(float* c, const uint32_t* a, const uint32_t* b)
{
    asm("mma.sync.aligned.m16n8k8.row.col.f32.tf32.tf32.f32 "
        "{%0,%1,%2,%3}, {%4,%5,%6,%7}, {%8,%9}, {%0,%1,%2,%3};"
        : "+f"(c[0]), "+f"(c[1]), "+f"(c[2]), "+f"(c[3])
        : "r"(a[0]), "r"(a[1]), "r"(a[2]), "r"(a[3]),
          "r"(b[0]), "r"(b[1]));
}

__device__ __forceinline__ void cp16(uint32_t dst, const float* src)
{
    asm volatile("cp.async.cg.shared.global [%0], [%1], 16;\n" :: "r"(dst), "l"(src));
}
#define CP_COMMIT()  asm volatile("cp.async.commit_group;\n" ::: "memory")
#define CP_WAIT1()   asm volatile("cp.async.wait_group 1;\n" ::: "memory")

// ---------------- prep: RNA-round all 4 weight matrices, one launch ---------
#define WN4 (OUTD * OUTD / 4)   // 65536 float4 per matrix
__global__ void round_all(const float4* __restrict__ s0, const float4* __restrict__ s1,
                          const float4* __restrict__ s2, const float4* __restrict__ s3)
{
    const int i = blockIdx.x * blockDim.x + threadIdx.x;   // 0 .. 4*WN4-1
    const int w = i >> 16;            // WN4 = 65536 = 2^16 -> matrix id
    const int r = i & (WN4 - 1);
    const float4* src = (w == 0) ? s0 : (w == 1) ? s1 : (w == 2) ? s2 : s3;
    float4 v = src[r];
    v.x = cvt_rna_tf32(v.x); v.y = cvt_rna_tf32(v.y);
    v.z = cvt_rna_tf32(v.z); v.w = cvt_rna_tf32(v.w);
    ((float4*)g_wr)[i] = v;
}

// ---------------- tf32 tensor-core GEMM (R6-measured body) ------------------
// C = (A[M,512] @ B[512,512] + bias) * scale
// CTA 128x128, BK=32, 128 threads: 4 warps in 2x2, warp tile 64x64.
// 3-stage cp.async pipeline, wait_group 1.
// MODE 0: fp32 out + tf32 RNA rounding (x). MODE 1: fp16 out (q/k/v).
#define BM 128
#define BN 128
#define BK 32
#define ASTR 36
#define BSTR 136
#define AS_STG (BM * ASTR)
#define BS_STG (BK * BSTR)
#define STG    (AS_STG + BS_STG)
#define NSTAGE 3
#define GSMEM_BYTES (NSTAGE * STG * 4)
#define KITERS (512 / BK)

template<int MODE>
__global__ __launch_bounds__(128, 2)
void gemm_tf32(const float* __restrict__ A, const float* __restrict__ B,
               const float* __restrict__ bias, void* __restrict__ Cout,
               float scale)
{
    extern __shared__ float sm[];
    const uint32_t smem_u = (uint32_t)__cvta_generic_to_shared(sm);

    const int tid  = threadIdx.x;
    const int lane = tid & 31;
    const int wid  = tid >> 5;
    const int brow = blockIdx.y * BM;
    const int bcol = blockIdx.x * BN;
    const int m0   = (wid >> 1) * 64;
    const int n0   = (wid & 1) * 64;
    const int lq   = lane >> 2;
    const int lr   = lane & 3;

    const int a_kc = tid & 7;
    const int a_r0 = tid >> 3;
    const int b_kc = tid & 31;
    const int b_r0 = tid >> 5;

    float acc[4][8][4];
#pragma unroll
    for (int mt = 0; mt < 4; mt++)
#pragma unroll
        for (int nt = 0; nt < 8; nt++)
#pragma unroll
            for (int r = 0; r < 4; r++) acc[mt][nt][r] = 0.f;

    auto load_stage = [&](int s, int kt) {
        const int k0 = kt * BK;
        const uint32_t abase = smem_u + (uint32_t)(s * STG) * 4u;
        const uint32_t bbase = abase + (uint32_t)AS_STG * 4u;
#pragma unroll
        for (int p = 0; p < 8; p++) {
            const int m = a_r0 + p * 16;
            cp16(abase + (uint32_t)(m * ASTR + a_kc * 4) * 4u,
                 A + (size_t)(brow + m) * 512 + k0 + a_kc * 4);
        }
#pragma unroll
        for (int p = 0; p < 8; p++) {
            const int k = b_r0 + p * 4;
            cp16(bbase + (uint32_t)(k * BSTR + b_kc * 4) * 4u,
                 B + (size_t)(k0 + k) * 512 + bcol + b_kc * 4);
        }
    };

    load_stage(0, 0); CP_COMMIT();
    load_stage(1, 1); CP_COMMIT();

    int st = 0;
    for (int it = 0; it < KITERS; ++it) {
        CP_WAIT1();
        __syncthreads();

        const float* As = sm + st * STG;
        const float* Bs = As + AS_STG;

#pragma unroll
        for (int g = 0; g < 4; ++g) {
            uint32_t bf[8][2];
#pragma unroll
            for (int nt = 0; nt < 8; nt++) {
                const int n = n0 + nt * 8 + lq;
                bf[nt][0] = __float_as_uint(Bs[(g * 8 + lr) * BSTR + n]);
                bf[nt][1] = __float_as_uint(Bs[(g * 8 + 4 + lr) * BSTR + n]);
            }
#pragma unroll
            for (int mt = 0; mt < 4; mt++) {
                const int row = m0 + mt * 16 + lq;
                uint32_t af[4];
                af[0] = __float_as_uint(As[(row)     * ASTR + g * 8 + lr]);
                af[1] = __float_as_uint(As[(row + 8) * ASTR + g * 8 + lr]);
                af[2] = __float_as_uint(As[(row)     * ASTR + g * 8 + 4 + lr]);
                af[3] = __float_as_uint(As[(row + 8) * ASTR + g * 8 + 4 + lr]);
#pragma unroll
                for (int nt = 0; nt < 8; nt++)
                    mma_tf32(acc[mt][nt], af, bf[nt]);
            }
        }

        const int nx = it + 2;
        if (nx < KITERS) load_stage(nx % NSTAGE, nx);
        CP_COMMIT();
        st = (st == NSTAGE - 1) ? 0 : st + 1;
    }

    // ---- epilogue ----
#pragma unroll
    for (int mt = 0; mt < 4; mt++) {
        const int row = brow + m0 + mt * 16 + lq;
#pragma unroll
        for (int nt = 0; nt < 8; nt++) {
            const int colb = bcol + n0 + nt * 8 + 2 * lr;
            const float b0 = __ldg(bias + colb);
            const float b1 = __ldg(bias + colb + 1);
            float2 o0, o1;
            o0.x = (acc[mt][nt][0] + b0) * scale;
            o0.y = (acc[mt][nt][1] + b1) * scale;
            o1.x = (acc[mt][nt][2] + b0) * scale;
            o1.y = (acc[mt][nt][3] + b1) * scale;
            if (MODE == 0) {
                float* C = (float*)Cout;
                o0.x = cvt_rna_tf32(o0.x); o0.y = cvt_rna_tf32(o0.y);
                o1.x = cvt_rna_tf32(o1.x); o1.y = cvt_rna_tf32(o1.y);
                *(float2*)(C + (size_t)row * 512 + colb)       = o0;
                *(float2*)(C + (size_t)(row + 8) * 512 + colb) = o1;
            } else {
                __half* C = (__half*)Cout;
                *(__half2*)(C + (size_t)row * 512 + colb)       = __floats2half2_rn(o0.x, o0.y);
                *(__half2*)(C + (size_t)(row + 8) * 512 + colb) = __floats2half2_rn(o1.x, o1.y);
            }
        }
    }
}

// ---------------- CSR build -------------------------------------------------
__global__ void count_kernel(const int* __restrict__ row)
{
    const int e = blockIdx.x * blockDim.x + threadIdx.x;
    if (e < EE) atomicAdd(&g_cnt[row[e]], 1);
}

__global__ void scan_kernel()
{
    __shared__ int sh[512];
    const int t = threadIdx.x;
    const int base = t * 64;
    int s = 0;
#pragma unroll 4
    for (int i = 0; i < 64; i++) s += g_cnt[base + i];
    sh[t] = s;
    __syncthreads();
    for (int off = 1; off < 512; off <<= 1) {
        int v = (t >= off) ? sh[t - off] : 0;
        __syncthreads();
        sh[t] += v;
        __syncthreads();
    }
    int run = sh[t] - s;
    for (int i = 0; i < 64; i++) {
        g_off[base + i] = run;
        g_cur[base + i] = run;
        run += g_cnt[base + i];
    }
    if (t == 511) g_off[NN] = run;
}

__global__ void scatter_kernel(const int* __restrict__ row, const int* __restrict__ col)
{
    const int e = blockIdx.x * blockDim.x + threadIdx.x;
    if (e < EE) {
        const int p = atomicAdd(&g_cur[row[e]], 1);
        g_ecol[p] = col[e];
    }
}

// ---------------- fused SDDMM + softmax + SPMM (fp16 gathers) ---------------
// One block per node, one warp per head; math in fp32, storage fp16.
__global__ __launch_bounds__(256)
void attn_kernel(float* __restrict__ out)
{
    const int node = blockIdx.x;
    const int head = threadIdx.x >> 5;
    const int lane = threadIdx.x & 31;
    const int beg = g_off[node];
    const int end = g_off[node + 1];

    const size_t hoff = (size_t)head * DHH + lane * 2;
    const float2 qv = __half22float2(*(const __half2*)(g_q + (size_t)node * OUTD + hoff));

    float den1 = 0.f, den2 = 0.f;
    float2 acc1 = make_float2(0.f, 0.f);
    float2 acc2 = make_float2(0.f, 0.f);

    int j = beg;
    for (; j + 1 < end; j += 2) {
        const int ca = __ldg(g_ecol + j);
        const int cb = __ldg(g_ecol + j + 1);
        const float2 ka = __half22float2(*(const __half2*)(g_k + (size_t)ca * OUTD + hoff));
        const float2 kb = __half22float2(*(const __half2*)(g_k + (size_t)cb * OUTD + hoff));
        float sa = qv.x * ka.x + qv.y * ka.y;
        float sb = qv.x * kb.x + qv.y * kb.y;
#pragma unroll
        for (int off = 16; off; off >>= 1) {
            sa += __shfl_xor_sync(0xffffffffu, sa, off);
            sb += __shfl_xor_sync(0xffffffffu, sb, off);
        }
        const float2 va = __half22float2(*(const __half2*)(g_v + (size_t)ca * OUTD + hoff));
        const float2 vb = __half22float2(*(const __half2*)(g_v + (size_t)cb * OUTD + hoff));
        const float pa = __expf(sa);
        const float pb = __expf(sb);
        den1   += pa;
        acc1.x += pa * va.x;
        acc1.y += pa * va.y;
        den2   += pb;
        acc2.x += pb * vb.x;
        acc2.y += pb * vb.y;
    }
    if (j < end) {
        const int ca = __ldg(g_ecol + j);
        const float2 ka = __half22float2(*(const __half2*)(g_k + (size_t)ca * OUTD + hoff));
        float sa = qv.x * ka.x + qv.y * ka.y;
#pragma unroll
        for (int off = 16; off; off >>= 1)
            sa += __shfl_xor_sync(0xffffffffu, sa, off);
        const float2 va = __half22float2(*(const __half2*)(g_v + (size_t)ca * OUTD + hoff));
        const float pa = __expf(sa);
        den1   += pa;
        acc1.x += pa * va.x;
        acc1.y += pa * va.y;
    }

    const float den = den1 + den2;
    float2 acc;
    acc.x = acc1.x + acc2.x;
    acc.y = acc1.y + acc2.y;

    const float inv = (den > 0.f) ? (1.f / den) : 0.f;
    float2 o = make_float2(acc.x * inv, acc.y * inv);
    *(float2*)(out + (size_t)node * OUTD + hoff) = o;
}

// ---------------- launch ----------------------------------------------------
extern "C" void kernel_launch(void* const* d_in, const int* in_sizes, int n_in,
                              void* d_out, int out_size)
{
    const float* h    = (const float*)d_in[0];
    const int*   row  = (const int*)d_in[1];
    const int*   col  = (const int*)d_in[2];
    const float* W_in = (const float*)d_in[3];
    const float* b_in = (const float*)d_in[4];
    const float* W_q  = (const float*)d_in[5];
    const float* b_q  = (const float*)d_in[6];
    const float* W_k  = (const float*)d_in[7];
    const float* b_k  = (const float*)d_in[8];
    const float* W_v  = (const float*)d_in[9];
    const float* b_v  = (const float*)d_in[10];
    float* out = (float*)d_out;

    float *gwr, *gx;
    __half *gq, *gk, *gv;
    int* gcnt;
    cudaGetSymbolAddress((void**)&gwr, g_wr);
    cudaGetSymbolAddress((void**)&gx, g_x);
    cudaGetSymbolAddress((void**)&gq, g_q);
    cudaGetSymbolAddress((void**)&gk, g_k);
    cudaGetSymbolAddress((void**)&gv, g_v);
    cudaGetSymbolAddress((void**)&gcnt, g_cnt);

    cudaFuncSetAttribute(gemm_tf32<0>, cudaFuncAttributeMaxDynamicSharedMemorySize, GSMEM_BYTES);
    cudaFuncSetAttribute(gemm_tf32<1>, cudaFuncAttributeMaxDynamicSharedMemorySize, GSMEM_BYTES);

    // prep: RNA-round all 4 weight matrices in one launch
    round_all<<<4 * WN4 / 256, 256>>>((const float4*)W_in, (const float4*)W_q,
                                      (const float4*)W_k,  (const float4*)W_v);

    const dim3 ggrid(512 / BN, NN / BM);  // (4, 256)
    gemm_tf32<0><<<ggrid, 128, GSMEM_BYTES>>>(h,  gwr + 0 * OUTD * OUTD, b_in, gx, 1.0f);
    gemm_tf32<1><<<ggrid, 128, GSMEM_BYTES>>>(gx, gwr + 1 * OUTD * OUTD, b_q,  gq, 0.125f);
    gemm_tf32<1><<<ggrid, 128, GSMEM_BYTES>>>(gx, gwr + 2 * OUTD * OUTD, b_k,  gk, 1.0f);
    gemm_tf32<1><<<ggrid, 128, GSMEM_BYTES>>>(gx, gwr + 3 * OUTD * OUTD, b_v,  gv, 1.0f);

    cudaMemsetAsync(gcnt, 0, NN * sizeof(int));
    count_kernel<<<EE / 256, 256>>>(row);
    scan_kernel<<<1, 512>>>();
    scatter_kernel<<<EE / 256, 256>>>(row, col);

    attn_kernel<<<NN, 256>>>(out);
}

// round 13
// speedup vs baseline: 1.5386x; 1.5386x over previous
#include <cuda_runtime.h>
#include <cuda_fp16.h>
#include <stdint.h>

// Problem constants (fixed by the reference)
#define NN    32768
#define EE    262144
#define OUTD  512
#define HH    8
#define DHH   64

// ---------------- scratch (device globals; no allocation allowed) ----------
__device__ float  g_wr[4 * OUTD * OUTD];   // RNA-rounded weights
__device__ float  g_x[NN * OUTD];          // x, stored already tf32-rounded
__device__ __half g_q[NN * OUTD];          // q/k/v stored fp16 (RN)
__device__ __half g_k[NN * OUTD];
__device__ __half g_v[NN * OUTD];
__device__ int    g_cnt[NN];
__device__ int    g_off[NN + 1];
__device__ int    g_cur[NN];
__device__ int    g_ecol[EE];

// ---------------- tf32 helpers ---------------------------------------------
__device__ __forceinline__ float cvt_rna_tf32(float x)
{
    float r;
    asm("cvt.rna.tf32.f32 %0, %1;" : "=f"(r) : "f"(x));
    return r;
}

__device__ __forceinline__ void mma_tf32(float* c, const uint32_t* a, const uint32_t* b)
{
    asm("mma.sync.aligned.m16n8k8.row.col.f32.tf32.tf32.f32 "
        "{%0,%1,%2,%3}, {%4,%5,%6,%7}, {%8,%9}, {%0,%1,%2,%3};"
        : "+f"(c[0]), "+f"(c[1]), "+f"(c[2]), "+f"(c[3])
        : "r"(a[0]), "r"(a[1]), "r"(a[2]), "r"(a[3]),
          "r"(b[0]), "r"(b[1]));
}

__device__ __forceinline__ void cp16(uint32_t dst, const float* src)
{
    asm volatile("cp.async.cg.shared.global [%0], [%1], 16;\n" :: "r"(dst), "l"(src));
}
#define CP_COMMIT()  asm volatile("cp.async.commit_group;\n" ::: "memory")
#define CP_WAIT1()   asm volatile("cp.async.wait_group 1;\n" ::: "memory")

// ---------------- prep: RNA-round all 4 weight matrices, one launch ---------
#define WN4 (OUTD * OUTD / 4)   // 65536 float4 per matrix
__global__ void round_all(const float4* __restrict__ s0, const float4* __restrict__ s1,
                          const float4* __restrict__ s2, const float4* __restrict__ s3)
{
    const int i = blockIdx.x * blockDim.x + threadIdx.x;   // 0 .. 4*WN4-1
    const int w = i >> 16;            // WN4 = 65536 = 2^16 -> matrix id
    const int r = i & (WN4 - 1);
    const float4* src = (w == 0) ? s0 : (w == 1) ? s1 : (w == 2) ? s2 : s3;
    float4 v = src[r];
    v.x = cvt_rna_tf32(v.x); v.y = cvt_rna_tf32(v.y);
    v.z = cvt_rna_tf32(v.z); v.w = cvt_rna_tf32(v.w);
    ((float4*)g_wr)[i] = v;
}

// ---------------- tf32 tensor-core GEMM (R6-measured body) ------------------
// C = (A[M,512] @ B[512,512] + bias) * scale
// CTA 128x128, BK=32, 128 threads: 4 warps in 2x2, warp tile 64x64.
// 3-stage cp.async pipeline, wait_group 1.
// MODE 0: fp32 out + tf32 RNA rounding (x). MODE 1: fp16 out (q/k/v).
#define BM 128
#define BN 128
#define BK 32
#define ASTR 36
#define BSTR 136
#define AS_STG (BM * ASTR)
#define BS_STG (BK * BSTR)
#define STG    (AS_STG + BS_STG)
#define NSTAGE 3
#define GSMEM_BYTES (NSTAGE * STG * 4)
#define KITERS (512 / BK)

template<int MODE>
__global__ __launch_bounds__(128, 2)
void gemm_tf32(const float* __restrict__ A, const float* __restrict__ B,
               const float* __restrict__ bias, void* __restrict__ Cout,
               float scale)
{
    extern __shared__ float sm[];
    const uint32_t smem_u = (uint32_t)__cvta_generic_to_shared(sm);

    const int tid  = threadIdx.x;
    const int lane = tid & 31;
    const int wid  = tid >> 5;
    const int brow = blockIdx.y * BM;
    const int bcol = blockIdx.x * BN;
    const int m0   = (wid >> 1) * 64;
    const int n0   = (wid & 1) * 64;
    const int lq   = lane >> 2;
    const int lr   = lane & 3;

    const int a_kc = tid & 7;
    const int a_r0 = tid >> 3;
    const int b_kc = tid & 31;
    const int b_r0 = tid >> 5;

    float acc[4][8][4];
#pragma unroll
    for (int mt = 0; mt < 4; mt++)
#pragma unroll
        for (int nt = 0; nt < 8; nt++)
#pragma unroll
            for (int r = 0; r < 4; r++) acc[mt][nt][r] = 0.f;

    auto load_stage = [&](int s, int kt) {
        const int k0 = kt * BK;
        const uint32_t abase = smem_u + (uint32_t)(s * STG) * 4u;
        const uint32_t bbase = abase + (uint32_t)AS_STG * 4u;
#pragma unroll
        for (int p = 0; p < 8; p++) {
            const int m = a_r0 + p * 16;
            cp16(abase + (uint32_t)(m * ASTR + a_kc * 4) * 4u,
                 A + (size_t)(brow + m) * 512 + k0 + a_kc * 4);
        }
#pragma unroll
        for (int p = 0; p < 8; p++) {
            const int k = b_r0 + p * 4;
            cp16(bbase + (uint32_t)(k * BSTR + b_kc * 4) * 4u,
                 B + (size_t)(k0 + k) * 512 + bcol + b_kc * 4);
        }
    };

    load_stage(0, 0); CP_COMMIT();
    load_stage(1, 1); CP_COMMIT();

    int st = 0;
    for (int it = 0; it < KITERS; ++it) {
        CP_WAIT1();
        __syncthreads();

        const float* As = sm + st * STG;
        const float* Bs = As + AS_STG;

#pragma unroll
        for (int g = 0; g < 4; ++g) {
            uint32_t bf[8][2];
#pragma unroll
            for (int nt = 0; nt < 8; nt++) {
                const int n = n0 + nt * 8 + lq;
                bf[nt][0] = __float_as_uint(Bs[(g * 8 + lr) * BSTR + n]);
                bf[nt][1] = __float_as_uint(Bs[(g * 8 + 4 + lr) * BSTR + n]);
            }
#pragma unroll
            for (int mt = 0; mt < 4; mt++) {
                const int row = m0 + mt * 16 + lq;
                uint32_t af[4];
                af[0] = __float_as_uint(As[(row)     * ASTR + g * 8 + lr]);
                af[1] = __float_as_uint(As[(row + 8) * ASTR + g * 8 + lr]);
                af[2] = __float_as_uint(As[(row)     * ASTR + g * 8 + 4 + lr]);
                af[3] = __float_as_uint(As[(row + 8) * ASTR + g * 8 + 4 + lr]);
#pragma unroll
                for (int nt = 0; nt < 8; nt++)
                    mma_tf32(acc[mt][nt], af, bf[nt]);
            }
        }

        const int nx = it + 2;
        if (nx < KITERS) load_stage(nx % NSTAGE, nx);
        CP_COMMIT();
        st = (st == NSTAGE - 1) ? 0 : st + 1;
    }

    // ---- epilogue ----
#pragma unroll
    for (int mt = 0; mt < 4; mt++) {
        const int row = brow + m0 + mt * 16 + lq;
#pragma unroll
        for (int nt = 0; nt < 8; nt++) {
            const int colb = bcol + n0 + nt * 8 + 2 * lr;
            const float b0 = __ldg(bias + colb);
            const float b1 = __ldg(bias + colb + 1);
            float2 o0, o1;
            o0.x = (acc[mt][nt][0] + b0) * scale;
            o0.y = (acc[mt][nt][1] + b1) * scale;
            o1.x = (acc[mt][nt][2] + b0) * scale;
            o1.y = (acc[mt][nt][3] + b1) * scale;
            if (MODE == 0) {
                float* C = (float*)Cout;
                o0.x = cvt_rna_tf32(o0.x); o0.y = cvt_rna_tf32(o0.y);
                o1.x = cvt_rna_tf32(o1.x); o1.y = cvt_rna_tf32(o1.y);
                *(float2*)(C + (size_t)row * 512 + colb)       = o0;
                *(float2*)(C + (size_t)(row + 8) * 512 + colb) = o1;
            } else {
                __half* C = (__half*)Cout;
                *(__half2*)(C + (size_t)row * 512 + colb)       = __floats2half2_rn(o0.x, o0.y);
                *(__half2*)(C + (size_t)(row + 8) * 512 + colb) = __floats2half2_rn(o1.x, o1.y);
            }
        }
    }
}

// ---------------- CSR build -------------------------------------------------
__global__ void count_kernel(const int* __restrict__ row)
{
    const int e = blockIdx.x * blockDim.x + threadIdx.x;
    if (e < EE) atomicAdd(&g_cnt[row[e]], 1);
}

__global__ void scan_kernel()
{
    __shared__ int sh[512];
    const int t = threadIdx.x;
    const int base = t * 64;
    int s = 0;
#pragma unroll 4
    for (int i = 0; i < 64; i++) s += g_cnt[base + i];
    sh[t] = s;
    __syncthreads();
    for (int off = 1; off < 512; off <<= 1) {
        int v = (t >= off) ? sh[t - off] : 0;
        __syncthreads();
        sh[t] += v;
        __syncthreads();
    }
    int run = sh[t] - s;
    for (int i = 0; i < 64; i++) {
        g_off[base + i] = run;
        g_cur[base + i] = run;
        run += g_cnt[base + i];
    }
    if (t == 511) g_off[NN] = run;
}

__global__ void scatter_kernel(const int* __restrict__ row, const int* __restrict__ col)
{
    const int e = blockIdx.x * blockDim.x + threadIdx.x;
    if (e < EE) {
        const int p = atomicAdd(&g_cur[row[e]], 1);
        g_ecol[p] = col[e];
    }
}

// ---------------- fused SDDMM + softmax + SPMM (fp16 gathers) ---------------
// One block per node, one warp per head; math in fp32, storage fp16.
__global__ __launch_bounds__(256)
void attn_kernel(float* __restrict__ out)
{
    const int node = blockIdx.x;
    const int head = threadIdx.x >> 5;
    const int lane = threadIdx.x & 31;
    const int beg = g_off[node];
    const int end = g_off[node + 1];

    const size_t hoff = (size_t)head * DHH + lane * 2;
    const float2 qv = __half22float2(*(const __half2*)(g_q + (size_t)node * OUTD + hoff));

    float den1 = 0.f, den2 = 0.f;
    float2 acc1 = make_float2(0.f, 0.f);
    float2 acc2 = make_float2(0.f, 0.f);

    int j = beg;
    for (; j + 1 < end; j += 2) {
        const int ca = __ldg(g_ecol + j);
        const int cb = __ldg(g_ecol + j + 1);
        const float2 ka = __half22float2(*(const __half2*)(g_k + (size_t)ca * OUTD + hoff));
        const float2 kb = __half22float2(*(const __half2*)(g_k + (size_t)cb * OUTD + hoff));
        float sa = qv.x * ka.x + qv.y * ka.y;
        float sb = qv.x * kb.x + qv.y * kb.y;
#pragma unroll
        for (int off = 16; off; off >>= 1) {
            sa += __shfl_xor_sync(0xffffffffu, sa, off);
            sb += __shfl_xor_sync(0xffffffffu, sb, off);
        }
        const float2 va = __half22float2(*(const __half2*)(g_v + (size_t)ca * OUTD + hoff));
        const float2 vb = __half22float2(*(const __half2*)(g_v + (size_t)cb * OUTD + hoff));
        const float pa = __expf(sa);
        const float pb = __expf(sb);
        den1   += pa;
        acc1.x += pa * va.x;
        acc1.y += pa * va.y;
        den2   += pb;
        acc2.x += pb * vb.x;
        acc2.y += pb * vb.y;
    }
    if (j < end) {
        const int ca = __ldg(g_ecol + j);
        const float2 ka = __half22float2(*(const __half2*)(g_k + (size_t)ca * OUTD + hoff));
        float sa = qv.x * ka.x + qv.y * ka.y;
#pragma unroll
        for (int off = 16; off; off >>= 1)
            sa += __shfl_xor_sync(0xffffffffu, sa, off);
        const float2 va = __half22float2(*(const __half2*)(g_v + (size_t)ca * OUTD + hoff));
        const float pa = __expf(sa);
        den1   += pa;
        acc1.x += pa * va.x;
        acc1.y += pa * va.y;
    }

    const float den = den1 + den2;
    float2 acc;
    acc.x = acc1.x + acc2.x;
    acc.y = acc1.y + acc2.y;

    const float inv = (den > 0.f) ? (1.f / den) : 0.f;
    float2 o = make_float2(acc.x * inv, acc.y * inv);
    *(float2*)(out + (size_t)node * OUTD + hoff) = o;
}

// ---------------- launch ----------------------------------------------------
extern "C" void kernel_launch(void* const* d_in, const int* in_sizes, int n_in,
                              void* d_out, int out_size)
{
    const float* h    = (const float*)d_in[0];
    const int*   row  = (const int*)d_in[1];
    const int*   col  = (const int*)d_in[2];
    const float* W_in = (const float*)d_in[3];
    const float* b_in = (const float*)d_in[4];
    const float* W_q  = (const float*)d_in[5];
    const float* b_q  = (const float*)d_in[6];
    const float* W_k  = (const float*)d_in[7];
    const float* b_k  = (const float*)d_in[8];
    const float* W_v  = (const float*)d_in[9];
    const float* b_v  = (const float*)d_in[10];
    float* out = (float*)d_out;

    float *gwr, *gx;
    __half *gq, *gk, *gv;
    int* gcnt;
    cudaGetSymbolAddress((void**)&gwr, g_wr);
    cudaGetSymbolAddress((void**)&gx, g_x);
    cudaGetSymbolAddress((void**)&gq, g_q);
    cudaGetSymbolAddress((void**)&gk, g_k);
    cudaGetSymbolAddress((void**)&gv, g_v);
    cudaGetSymbolAddress((void**)&gcnt, g_cnt);

    cudaFuncSetAttribute(gemm_tf32<0>, cudaFuncAttributeMaxDynamicSharedMemorySize, GSMEM_BYTES);
    cudaFuncSetAttribute(gemm_tf32<1>, cudaFuncAttributeMaxDynamicSharedMemorySize, GSMEM_BYTES);

    // prep: RNA-round all 4 weight matrices in one launch
    round_all<<<4 * WN4 / 256, 256>>>((const float4*)W_in, (const float4*)W_q,
                                      (const float4*)W_k,  (const float4*)W_v);

    const dim3 ggrid(512 / BN, NN / BM);  // (4, 256)
    gemm_tf32<0><<<ggrid, 128, GSMEM_BYTES>>>(h,  gwr + 0 * OUTD * OUTD, b_in, gx, 1.0f);
    gemm_tf32<1><<<ggrid, 128, GSMEM_BYTES>>>(gx, gwr + 1 * OUTD * OUTD, b_q,  gq, 0.125f);
    gemm_tf32<1><<<ggrid, 128, GSMEM_BYTES>>>(gx, gwr + 2 * OUTD * OUTD, b_k,  gk, 1.0f);
    gemm_tf32<1><<<ggrid, 128, GSMEM_BYTES>>>(gx, gwr + 3 * OUTD * OUTD, b_v,  gv, 1.0f);

    cudaMemsetAsync(gcnt, 0, NN * sizeof(int));
    count_kernel<<<EE / 256, 256>>>(row);
    scan_kernel<<<1, 512>>>();
    scatter_kernel<<<EE / 256, 256>>>(row, col);

    attn_kernel<<<NN, 256>>>(out);
}